// round 1
// baseline (speedup 1.0000x reference)
#include <cuda_runtime.h>

#define Bb   4
#define NN   2048
#define FIN  256
#define FOUT 128
#define HH   4
#define TI   32
#define TJ   32
#define NEG  0.2f

// scratch (no cudaMalloc allowed)
__device__ float  g_Wh[Bb * NN * FOUT];        // 4 MB
__device__ float4 g_ipack[Bb * HH * NN];       // (el, exp(el), exp(0.2 el), 0)
__device__ float4 g_jpack[Bb * HH * NN];       // (er, exp(er), exp(0.2 er), 0)

// ---------------------------------------------------------------------------
// Kernel 1: Wh[b,n,o] = sum_f h[b,n,f] * W_w[o,f] + W_b[o]
// grid: 8192/16 = 512 blocks, 128 threads (thread = output column o)
// ---------------------------------------------------------------------------
__global__ __launch_bounds__(128) void wh_kernel(const float* __restrict__ h,
                                                 const float* __restrict__ Ww,
                                                 const float* __restrict__ Wb)
{
    __shared__ float hs[16][FIN];          // 16 KB
    const int t    = threadIdx.x;
    const int row0 = blockIdx.x * 16;

    const float4* src = (const float4*)(h + (size_t)row0 * FIN);
    float4*       dst = (float4*)hs;
#pragma unroll
    for (int q = 0; q < 8; q++) dst[t + 128 * q] = src[t + 128 * q];
    __syncthreads();

    const int o = t;
    const float* wrow = Ww + o * FIN;
    float acc[16];
#pragma unroll
    for (int r = 0; r < 16; r++) acc[r] = 0.f;

#pragma unroll 4
    for (int k = 0; k < FIN; k += 4) {
        float4 wv = *(const float4*)(wrow + k);
#pragma unroll
        for (int r = 0; r < 16; r++) {
            float4 hv = *(const float4*)&hs[r][k];
            acc[r] += hv.x * wv.x;
            acc[r] += hv.y * wv.y;
            acc[r] += hv.z * wv.z;
            acc[r] += hv.w * wv.w;
        }
    }
    const float bias = Wb[o];
#pragma unroll
    for (int r = 0; r < 16; r++)
        g_Wh[(size_t)(row0 + r) * FOUT + o] = acc[r] + bias;
}

// ---------------------------------------------------------------------------
// Kernel 2: per (b,h,n): el = Wh . a_left[h], er = Wh . a_right[h], plus exps.
// grid: 1024 blocks x 256 threads, one warp per (b,n) row.
// ---------------------------------------------------------------------------
__global__ __launch_bounds__(256) void pack_kernel(const float* __restrict__ attn_w)
{
    const int t    = threadIdx.x;
    const int warp = t >> 5;
    const int lane = t & 31;
    const int row  = blockIdx.x * 8 + warp;     // 0..8191
    const int b    = row >> 11;
    const int n    = row & (NN - 1);

    float4 wh = *(const float4*)(g_Wh + (size_t)row * FOUT + lane * 4);

#pragma unroll
    for (int hh = 0; hh < HH; hh++) {
        float4 al = *(const float4*)(attn_w + hh * 2 * FOUT + lane * 4);
        float4 ar = *(const float4*)(attn_w + hh * 2 * FOUT + FOUT + lane * 4);
        float sl = wh.x * al.x + wh.y * al.y + wh.z * al.z + wh.w * al.w;
        float sr = wh.x * ar.x + wh.y * ar.y + wh.z * ar.z + wh.w * ar.w;
#pragma unroll
        for (int off = 16; off > 0; off >>= 1) {
            sl += __shfl_xor_sync(0xffffffffu, sl, off);
            sr += __shfl_xor_sync(0xffffffffu, sr, off);
        }
        if (lane == 0) {
            const int idx = (b * HH + hh) * NN + n;
            g_ipack[idx] = make_float4(sl, expf(sl), expf(NEG * sl), 0.f);
            g_jpack[idx] = make_float4(sr, expf(sr), expf(NEG * sr), 0.f);
        }
    }
}

// ---------------------------------------------------------------------------
// Kernel 3 (main): fused masked-softmax(rank-1 logits) @ Wh, all 4 heads,
// head-mean + ReLU epilogue.
// grid: (N/TI=64, B=4), 256 threads. Per block: 32 output rows.
// ---------------------------------------------------------------------------
__global__ __launch_bounds__(256, 2) void gat_main(const int* __restrict__ adj,
                                                   float* __restrict__ out)
{
    const int it  = blockIdx.x;       // i-tile
    const int b   = blockIdx.y;
    const int i0g = it * TI;

    __shared__ float  whs[TJ][FOUT];      // 16 KB  Wh j-tile (fp32)
    __shared__ float  ws[HH][TI][TJ];     // 16 KB  unnormalized attn weights
    __shared__ float4 jps[HH][TJ];        //  2 KB  (er, e^er, e^.2er)
    __shared__ float  zbuf[HH][TI][8];    //  4 KB  partial row sums

    const int t  = threadIdx.x;
    // weight-generation mapping: thread -> (row gi, 4 consecutive j at gj*4)
    const int gi = t >> 3;                // 0..31
    const int gj = t & 7;                 // 0..7
    // GEMM mapping: warp -> 4 rows, lane -> 4 output cols
    const int wi = t >> 5;                // warp 0..7 -> i0 = wi*4
    const int ln = t & 31;                // lane      -> o0 = ln*4

    float el[HH], A[HH], C[HH];
#pragma unroll
    for (int hh = 0; hh < HH; hh++) {
        float4 ip = g_ipack[(b * HH + hh) * NN + i0g + gi];
        el[hh] = ip.x; A[hh] = ip.y; C[hh] = ip.z;
    }
    float z[HH] = {0.f, 0.f, 0.f, 0.f};
    float acc[HH][4][4];
#pragma unroll
    for (int hh = 0; hh < HH; hh++)
#pragma unroll
        for (int ii = 0; ii < 4; ii++)
#pragma unroll
            for (int oo = 0; oo < 4; oo++) acc[hh][ii][oo] = 0.f;

    const long arow = (long)(i0g + gi) * NN;

    for (int jt = 0; jt < NN / TJ; jt++) {
        const int j0 = jt * TJ;

        // stage Wh tile (coalesced copy)
        {
            const float4* src = (const float4*)(g_Wh + (size_t)(b * NN + j0) * FOUT);
            float4* dst = (float4*)whs;
#pragma unroll
            for (int q = 0; q < 4; q++) dst[t + 256 * q] = src[t + 256 * q];
        }
        // stage j-packs
        if (t < HH * TJ) {
            const int hh = t >> 5, jj = t & 31;
            jps[hh][jj] = g_jpack[(b * HH + hh) * NN + j0 + jj];
        }
        __syncthreads();

        // generate unnormalized masked weights
        {
            int4 m4 = *(const int4*)(adj + arow + j0 + gj * 4);
            int mk[4] = {m4.x, m4.y, m4.z, m4.w};
#pragma unroll
            for (int hh = 0; hh < HH; hh++) {
#pragma unroll
                for (int k = 0; k < 4; k++) {
                    float4 jp = jps[hh][gj * 4 + k];
                    float wv = (el[hh] + jp.x > 0.f) ? A[hh] * jp.y : C[hh] * jp.z;
                    wv = mk[k] ? wv : 0.f;
                    z[hh] += wv;
                    ws[hh][gi][gj * 4 + k] = wv;
                }
            }
        }
        __syncthreads();

        // register-tiled GEMM: acc[h] += ws[h] @ whs
#pragma unroll 2
        for (int j = 0; j < TJ; j++) {
            float4 wh4 = *(const float4*)&whs[j][ln * 4];
#pragma unroll
            for (int hh = 0; hh < HH; hh++) {
                float w0 = ws[hh][wi * 4 + 0][j];
                float w1 = ws[hh][wi * 4 + 1][j];
                float w2 = ws[hh][wi * 4 + 2][j];
                float w3 = ws[hh][wi * 4 + 3][j];
                acc[hh][0][0] += w0 * wh4.x; acc[hh][0][1] += w0 * wh4.y;
                acc[hh][0][2] += w0 * wh4.z; acc[hh][0][3] += w0 * wh4.w;
                acc[hh][1][0] += w1 * wh4.x; acc[hh][1][1] += w1 * wh4.y;
                acc[hh][1][2] += w1 * wh4.z; acc[hh][1][3] += w1 * wh4.w;
                acc[hh][2][0] += w2 * wh4.x; acc[hh][2][1] += w2 * wh4.y;
                acc[hh][2][2] += w2 * wh4.z; acc[hh][2][3] += w2 * wh4.w;
                acc[hh][3][0] += w3 * wh4.x; acc[hh][3][1] += w3 * wh4.y;
                acc[hh][3][2] += w3 * wh4.z; acc[hh][3][3] += w3 * wh4.w;
            }
        }
        __syncthreads();
    }

    // reduce row sums Z
#pragma unroll
    for (int hh = 0; hh < HH; hh++) zbuf[hh][gi][gj] = z[hh];
    __syncthreads();

    float outv[4][4];
#pragma unroll
    for (int ii = 0; ii < 4; ii++)
#pragma unroll
        for (int oo = 0; oo < 4; oo++) outv[ii][oo] = 0.f;

#pragma unroll
    for (int hh = 0; hh < HH; hh++) {
#pragma unroll
        for (int ii = 0; ii < 4; ii++) {
            float Z = 0.f;
#pragma unroll
            for (int g = 0; g < 8; g++) Z += zbuf[hh][wi * 4 + ii][g];
            float inv = (Z > 0.f) ? 0.25f / Z : 0.f;   // head-mean folded in
#pragma unroll
            for (int oo = 0; oo < 4; oo++) outv[ii][oo] += acc[hh][ii][oo] * inv;
        }
    }

#pragma unroll
    for (int ii = 0; ii < 4; ii++) {
        float4 o4 = make_float4(fmaxf(outv[ii][0], 0.f), fmaxf(outv[ii][1], 0.f),
                                fmaxf(outv[ii][2], 0.f), fmaxf(outv[ii][3], 0.f));
        *(float4*)(out + (size_t)(b * NN + i0g + wi * 4 + ii) * FOUT + ln * 4) = o4;
    }
}

// ---------------------------------------------------------------------------
extern "C" void kernel_launch(void* const* d_in, const int* in_sizes, int n_in,
                              void* d_out, int out_size)
{
    const float* h      = (const float*)d_in[0];   // [4,2048,256] f32
    const int*   adj    = (const int*)d_in[1];     // [2048,2048] i32
    const float* W_w    = (const float*)d_in[2];   // [128,256] f32
    const float* W_b    = (const float*)d_in[3];   // [128] f32
    const float* attn_w = (const float*)d_in[4];   // [4,512] f32
    float* out = (float*)d_out;                    // [4,2048,128] f32

    wh_kernel<<<(Bb * NN) / 16, 128>>>(h, W_w, W_b);
    pack_kernel<<<(Bb * NN) / 8, 256>>>(attn_w);
    gat_main<<<dim3(NN / TI, Bb), 256>>>(adj, out);
}

// round 4
// speedup vs baseline: 2.8587x; 2.8587x over previous
#include <cuda_runtime.h>
#include <cstdint>

#define Bb   4
#define NN   2048
#define FIN  256
#define FOUT 128
#define HH   4
#define NEG  0.2f
#define TK   32
#define NT   (NN / TK)   // 64

// ---------------------------------------------------------------------------
// scratch (no cudaMalloc allowed)
// ---------------------------------------------------------------------------
__device__ float    g_Wh[Bb * NN * FOUT];        // [b][n][o]  4 MB
__device__ float4   g_ipack[Bb * HH * NN];       // (el, e^el, e^(.2el), 0)
__device__ float4   g_jpack[Bb * HH * NN];       // (er, e^er, e^(.2er), 0)
__device__ uint32_t g_adjbits[NN * (NN / 32)];   // 512 KB
__device__ uint2    g_Bfrag[Bb * NT * 2048];     // Wh in mma B-fragment order, tf32

// ---------------------------------------------------------------------------
__device__ __forceinline__ uint32_t f2tf32(float f) {
    uint32_t u;
    asm("cvt.rna.tf32.f32 %0, %1;" : "=r"(u) : "f"(f));
    return u;
}
__device__ __forceinline__ void mma_tf32(float& c0, float& c1, float& c2, float& c3,
                                         uint32_t a0, uint32_t a1, uint32_t a2, uint32_t a3,
                                         uint32_t b0, uint32_t b1) {
    asm volatile("mma.sync.aligned.m16n8k8.row.col.f32.tf32.tf32.f32 "
                 "{%0,%1,%2,%3}, {%4,%5,%6,%7}, {%8,%9}, {%0,%1,%2,%3};"
                 : "+f"(c0), "+f"(c1), "+f"(c2), "+f"(c3)
                 : "r"(a0), "r"(a1), "r"(a2), "r"(a3), "r"(b0), "r"(b1));
}

// ---------------------------------------------------------------------------
// Kernel 0: adj -> bitmask
// ---------------------------------------------------------------------------
__global__ __launch_bounds__(64) void adjbits_kernel(const int* __restrict__ adj)
{
    const int row = blockIdx.x, w = threadIdx.x;
    const int4* p = (const int4*)(adj + (size_t)row * NN + w * 32);
    uint32_t bits = 0;
#pragma unroll
    for (int q = 0; q < 8; q++) {
        int4 v = __ldg(p + q);
        bits |= (v.x ? 1u : 0u) << (q * 4 + 0);
        bits |= (v.y ? 1u : 0u) << (q * 4 + 1);
        bits |= (v.z ? 1u : 0u) << (q * 4 + 2);
        bits |= (v.w ? 1u : 0u) << (q * 4 + 3);
    }
    g_adjbits[row * (NN / 32) + w] = bits;
}

// ---------------------------------------------------------------------------
// Kernel 1: Wh = h @ W^T + b  (register-tiled fp32 GEMM)
// ---------------------------------------------------------------------------
__global__ __launch_bounds__(256) void wh2_kernel(const float* __restrict__ h,
                                                  const float* __restrict__ Ww,
                                                  const float* __restrict__ Wb)
{
    __shared__ float As[32][32];
    __shared__ float Bs[32][128];
    const int t     = threadIdx.x;
    const int grow0 = blockIdx.x * 32;
    const int col   = (t & 31) * 4;
    const int row0  = (t >> 5) * 4;

    float acc[4][4];
#pragma unroll
    for (int r = 0; r < 4; r++)
#pragma unroll
        for (int c = 0; c < 4; c++) acc[r][c] = 0.f;

    for (int kb = 0; kb < FIN; kb += 32) {
        {
            int r = t >> 3, k4 = (t & 7) * 4;
            *(float4*)&As[r][k4] =
                *(const float4*)(h + (size_t)(grow0 + r) * FIN + kb + k4);
        }
        {
            int o = t >> 1, kh = (t & 1) * 16;
#pragma unroll
            for (int s2 = 0; s2 < 4; s2++) {
                float4 v = *(const float4*)(Ww + (size_t)o * FIN + kb + kh + s2 * 4);
                Bs[kh + s2 * 4 + 0][o] = v.x;
                Bs[kh + s2 * 4 + 1][o] = v.y;
                Bs[kh + s2 * 4 + 2][o] = v.z;
                Bs[kh + s2 * 4 + 3][o] = v.w;
            }
        }
        __syncthreads();
#pragma unroll
        for (int k = 0; k < 32; k++) {
            float4 bv = *(const float4*)&Bs[k][col];
            float a0 = As[row0 + 0][k], a1 = As[row0 + 1][k];
            float a2 = As[row0 + 2][k], a3 = As[row0 + 3][k];
            acc[0][0] += a0 * bv.x; acc[0][1] += a0 * bv.y; acc[0][2] += a0 * bv.z; acc[0][3] += a0 * bv.w;
            acc[1][0] += a1 * bv.x; acc[1][1] += a1 * bv.y; acc[1][2] += a1 * bv.z; acc[1][3] += a1 * bv.w;
            acc[2][0] += a2 * bv.x; acc[2][1] += a2 * bv.y; acc[2][2] += a2 * bv.z; acc[2][3] += a2 * bv.w;
            acc[3][0] += a3 * bv.x; acc[3][1] += a3 * bv.y; acc[3][2] += a3 * bv.z; acc[3][3] += a3 * bv.w;
        }
        __syncthreads();
    }

    float4 bias = *(const float4*)(Wb + col);
    const float bc[4] = {bias.x, bias.y, bias.z, bias.w};
#pragma unroll
    for (int r = 0; r < 4; r++) {
        float4 o4 = make_float4(acc[r][0] + bc[0], acc[r][1] + bc[1],
                                acc[r][2] + bc[2], acc[r][3] + bc[3]);
        *(float4*)(g_Wh + (size_t)(grow0 + row0 + r) * FOUT + col) = o4;
    }
}

// ---------------------------------------------------------------------------
// Kernel 2: per (b,h,n): el/er dot products + exps (exact fp32)
// ---------------------------------------------------------------------------
__global__ __launch_bounds__(256) void pack_kernel(const float* __restrict__ attn_w)
{
    const int t    = threadIdx.x;
    const int warp = t >> 5;
    const int lane = t & 31;
    const int row  = blockIdx.x * 8 + warp;
    const int b    = row >> 11;
    const int n    = row & (NN - 1);

    float4 wh = *(const float4*)(g_Wh + (size_t)row * FOUT + lane * 4);
#pragma unroll
    for (int hh = 0; hh < HH; hh++) {
        float4 al = *(const float4*)(attn_w + hh * 2 * FOUT + lane * 4);
        float4 ar = *(const float4*)(attn_w + hh * 2 * FOUT + FOUT + lane * 4);
        float sl = wh.x * al.x + wh.y * al.y + wh.z * al.z + wh.w * al.w;
        float sr = wh.x * ar.x + wh.y * ar.y + wh.z * ar.z + wh.w * ar.w;
#pragma unroll
        for (int off = 16; off > 0; off >>= 1) {
            sl += __shfl_xor_sync(0xffffffffu, sl, off);
            sr += __shfl_xor_sync(0xffffffffu, sr, off);
        }
        if (lane == 0) {
            const int idx = (b * HH + hh) * NN + n;
            g_ipack[idx] = make_float4(sl, expf(sl), expf(NEG * sl), 0.f);
            g_jpack[idx] = make_float4(sr, expf(sr), expf(NEG * sr), 0.f);
        }
    }
}

// ---------------------------------------------------------------------------
// Kernel 3: repack Wh into B-fragment order (tf32) per (b, j-tile).
// slot s = (ks*16 + nt)*32 + lane; b0 = Wh[j0+ks*8+(lane&3)][nt*8+lane/4],
// b1 = same with j+4.
// ---------------------------------------------------------------------------
__global__ __launch_bounds__(256) void bfrag_kernel()
{
    const int jt = blockIdx.x, b = blockIdx.y, t = threadIdx.x;
    const size_t base = ((size_t)b * NT + jt) * 2048;
#pragma unroll
    for (int q = 0; q < 8; q++) {
        const int s    = q * 256 + t;
        const int lane = s & 31;
        const int nt   = (s >> 5) & 15;
        const int ks   = s >> 9;
        const int j    = jt * TK + ks * 8 + (lane & 3);
        const int o    = nt * 8 + (lane >> 2);
        float b0 = __ldg(&g_Wh[((size_t)(b * NN + j)) * FOUT + o]);
        float b1 = __ldg(&g_Wh[((size_t)(b * NN + j + 4)) * FOUT + o]);
        g_Bfrag[base + s] = make_uint2(f2tf32(b0), f2tf32(b1));
    }
}

// ---------------------------------------------------------------------------
// Kernel 4 (main): P(softmax-numerator) @ Wh via mma.sync tf32.
// Block = (b, 32 i-rows); M=128 rows pack 4 heads (m = i*4 + h); N = FOUT.
// 8 warps, 2x4 grid, warp tile 64x32.
// ---------------------------------------------------------------------------
// SMEM: Afrag[2][8][4][32] float4 (32KB) | Bfrag[2][4][16][32] float2 (32KB) | z[128]
#define SM_A(p, w, ks, ln)  ((((p) * 8 + (w)) * 4 + (ks)) * 32 + (ln))
#define SM_B(p, ks, nt, ln) ((((p) * 4 + (ks)) * 16 + (nt)) * 32 + (ln))
#define SMEM_BYTES (32768 + 32768 + 512)

__global__ __launch_bounds__(256, 2) void gat_main_mma(float* __restrict__ out)
{
    extern __shared__ char smem[];
    float4* Af = (float4*)smem;                  // fragment quads of P
    uint2*  Bf = (uint2*)(smem + 32768);         // fragment pairs of Wh (tf32)
    float*  zb = (float*)(smem + 65536);         // row sums Z[m]

    const int t    = threadIdx.x;
    const int w    = t >> 5;            // warp 0..7 (also generator m-tile id)
    const int lane = t & 31;
    const int mw   = w >> 2;            // 0..1
    const int nw   = w & 3;             // 0..3
    const int b    = blockIdx.y;
    const int i0   = blockIdx.x * 32;

    // generator lane decomposition
    const int r = lane >> 2;            // 0..7
    const int c = lane & 3;             // 0..3
    const int h = r & 3;
    const int iloc_lo = w * 4 + (r >> 2);         // local i of row m_lo
    const int iloc_hi = iloc_lo + 2;              // local i of row m_lo+8

    // row constants (fixed for whole kernel)
    const float4 ipl = __ldg(&g_ipack[(size_t)(b * HH + h) * NN + i0 + iloc_lo]);
    const float4 iph = __ldg(&g_ipack[(size_t)(b * HH + h) * NN + i0 + iloc_hi]);
    const float4* jbase = g_jpack + (size_t)(b * HH + h) * NN;
    const uint2*  bbase = g_Bfrag + (size_t)b * NT * 2048;

    float z_lo = 0.f, z_hi = 0.f;
    float acc[4][4][4];
#pragma unroll
    for (int a = 0; a < 4; a++)
#pragma unroll
        for (int n = 0; n < 4; n++)
#pragma unroll
            for (int k = 0; k < 4; k++) acc[a][n][k] = 0.f;

    // ---- produce tile jt into buffer p ----
    auto produce = [&](int jt, int p) {
        // stage B fragments: straight 16KB copy (tile = 2048 uint2)
        const uint4* srcv = (const uint4*)(bbase + (size_t)jt * 2048);
        uint4* dstv = (uint4*)(Bf + (size_t)p * 2048);
#pragma unroll
        for (int q = 0; q < 4; q++) dstv[q * 256 + t] = __ldg(srcv + q * 256 + t);

        // generate A fragments (P tile) for m-tile = w
        const uint32_t mw_lo = __ldg(&g_adjbits[(size_t)(i0 + iloc_lo) * 64 + jt]);
        const uint32_t mw_hi = __ldg(&g_adjbits[(size_t)(i0 + iloc_hi) * 64 + jt]);
#pragma unroll
        for (int ks = 0; ks < 4; ks++) {
            const int jA = jt * TK + ks * 8 + c;
            float4 jp0 = __ldg(jbase + jA);
            float4 jp4 = __ldg(jbase + jA + 4);

            float v0 = (ipl.x + jp0.x > 0.f) ? ipl.y * jp0.y : ipl.z * jp0.z;
            float v1 = (iph.x + jp0.x > 0.f) ? iph.y * jp0.y : iph.z * jp0.z;
            float v2 = (ipl.x + jp4.x > 0.f) ? ipl.y * jp4.y : ipl.z * jp4.z;
            float v3 = (iph.x + jp4.x > 0.f) ? iph.y * jp4.y : iph.z * jp4.z;

            v0 = ((mw_lo >> (ks * 8 + c))     & 1u) ? v0 : 0.f;
            v1 = ((mw_hi >> (ks * 8 + c))     & 1u) ? v1 : 0.f;
            v2 = ((mw_lo >> (ks * 8 + c + 4)) & 1u) ? v2 : 0.f;
            v3 = ((mw_hi >> (ks * 8 + c + 4)) & 1u) ? v3 : 0.f;

            z_lo += v0 + v2;
            z_hi += v1 + v3;

            Af[SM_A(p, w, ks, lane)] =
                make_float4(__uint_as_float(f2tf32(v0)), __uint_as_float(f2tf32(v1)),
                            __uint_as_float(f2tf32(v2)), __uint_as_float(f2tf32(v3)));
        }
    };

    // ---- consume tile in buffer p ----
    auto consume = [&](int p) {
#pragma unroll
        for (int ks = 0; ks < 4; ks++) {
            uint4 a[4];
            uint2 bfr[4];
#pragma unroll
            for (int mt = 0; mt < 4; mt++)
                a[mt] = *(uint4*)&Af[SM_A(p, mw * 4 + mt, ks, lane)];
#pragma unroll
            for (int nt = 0; nt < 4; nt++)
                bfr[nt] = Bf[SM_B(p, ks, nw * 4 + nt, lane)];
#pragma unroll
            for (int mt = 0; mt < 4; mt++)
#pragma unroll
                for (int nt = 0; nt < 4; nt++)
                    mma_tf32(acc[mt][nt][0], acc[mt][nt][1], acc[mt][nt][2], acc[mt][nt][3],
                             a[mt].x, a[mt].y, a[mt].z, a[mt].w,
                             bfr[nt].x, bfr[nt].y);
        }
    };

    produce(0, 0);
    __syncthreads();
    for (int jt = 0; jt < NT; jt++) {
        const int p = jt & 1;
        if (jt + 1 < NT) produce(jt + 1, p ^ 1);
        consume(p);
        __syncthreads();
    }

    // ---- Z reduction: sum over the 4 column-lanes of each generator row ----
    z_lo += __shfl_xor_sync(0xffffffffu, z_lo, 1);
    z_lo += __shfl_xor_sync(0xffffffffu, z_lo, 2);
    z_hi += __shfl_xor_sync(0xffffffffu, z_hi, 1);
    z_hi += __shfl_xor_sync(0xffffffffu, z_hi, 2);
    if (c == 0) {
        zb[w * 16 + r]     = z_lo;
        zb[w * 16 + r + 8] = z_hi;
    }
    __syncthreads();

    // ---- epilogue: scale by 0.25/Z, head-sum over m=4i..4i+3, ReLU, store ----
#pragma unroll
    for (int mt = 0; mt < 4; mt++) {
        const int mtile = mw * 4 + mt;
        const int m_a = mtile * 16 + r;
        const int m_b = m_a + 8;
        float zA = zb[m_a], zB = zb[m_b];
        float izA = (zA > 0.f) ? 0.25f / zA : 0.f;
        float izB = (zB > 0.f) ? 0.25f / zB : 0.f;
#pragma unroll
        for (int nt = 0; nt < 4; nt++) {
            float s0 = acc[mt][nt][0] * izA;
            float s1 = acc[mt][nt][1] * izA;
            float s2 = acc[mt][nt][2] * izB;
            float s3 = acc[mt][nt][3] * izB;
            // heads live on adjacent m-rows -> reduce over r-groups of 4
            s0 += __shfl_xor_sync(0xffffffffu, s0, 4);
            s0 += __shfl_xor_sync(0xffffffffu, s0, 8);
            s1 += __shfl_xor_sync(0xffffffffu, s1, 4);
            s1 += __shfl_xor_sync(0xffffffffu, s1, 8);
            s2 += __shfl_xor_sync(0xffffffffu, s2, 4);
            s2 += __shfl_xor_sync(0xffffffffu, s2, 8);
            s3 += __shfl_xor_sync(0xffffffffu, s3, 4);
            s3 += __shfl_xor_sync(0xffffffffu, s3, 8);
            if ((r & 3) == 0) {
                const int i_a = mtile * 4 + (r >> 2);     // local i (0..31)
                const int i_b = i_a + 2;
                const int col = nw * 32 + nt * 8 + c * 2;
                float2 oa = make_float2(fmaxf(s0, 0.f), fmaxf(s1, 0.f));
                float2 ob = make_float2(fmaxf(s2, 0.f), fmaxf(s3, 0.f));
                *(float2*)(out + ((size_t)(b * NN + i0 + i_a)) * FOUT + col) = oa;
                *(float2*)(out + ((size_t)(b * NN + i0 + i_b)) * FOUT + col) = ob;
            }
        }
    }
}

// ---------------------------------------------------------------------------
extern "C" void kernel_launch(void* const* d_in, const int* in_sizes, int n_in,
                              void* d_out, int out_size)
{
    const float* h      = (const float*)d_in[0];
    const int*   adj    = (const int*)d_in[1];
    const float* W_w    = (const float*)d_in[2];
    const float* W_b    = (const float*)d_in[3];
    const float* attn_w = (const float*)d_in[4];
    float* out = (float*)d_out;

    adjbits_kernel<<<NN, 64>>>(adj);
    wh2_kernel<<<(Bb * NN) / 32, 256>>>(h, W_w, W_b);
    pack_kernel<<<(Bb * NN) / 8, 256>>>(attn_w);
    bfrag_kernel<<<dim3(NT, Bb), 256>>>();

    cudaFuncSetAttribute(gat_main_mma,
                         cudaFuncAttributeMaxDynamicSharedMemorySize, SMEM_BYTES);
    gat_main_mma<<<dim3(NN / 32, Bb), 256, SMEM_BYTES>>>(out);
}

// round 5
// speedup vs baseline: 3.8136x; 1.3340x over previous
#include <cuda_runtime.h>
#include <cstdint>

#define Bb   4
#define NN   2048
#define FIN  256
#define FOUT 128
#define HH   4
#define NEG  0.2f
#define TK   32
#define NT   (NN / TK)   // 64

// ---------------------------------------------------------------------------
// scratch (no cudaMalloc allowed)
// ---------------------------------------------------------------------------
__device__ float    g_Wh[Bb * NN * FOUT];        // [b][n][o]  4 MB
__device__ float4   g_ipack[Bb * HH * NN];       // (el, e^el, e^(.2el), 0)
__device__ float4   g_jpack[Bb * HH * NN];       // (er, e^er, e^(.2er), 0)
__device__ uint32_t g_adjbits[NN * (NN / 32)];   // 512 KB
__device__ uint4    g_Bfrag4[Bb * NT * 1024];    // Wh B-fragments (tf32), paired

// ---------------------------------------------------------------------------
__device__ __forceinline__ uint32_t f2tf32(float f) {
    uint32_t u;
    asm("cvt.rna.tf32.f32 %0, %1;" : "=r"(u) : "f"(f));
    return u;
}
__device__ __forceinline__ void mma_tf32(float& c0, float& c1, float& c2, float& c3,
                                         uint32_t a0, uint32_t a1, uint32_t a2, uint32_t a3,
                                         uint32_t b0, uint32_t b1) {
    asm volatile("mma.sync.aligned.m16n8k8.row.col.f32.tf32.tf32.f32 "
                 "{%0,%1,%2,%3}, {%4,%5,%6,%7}, {%8,%9}, {%0,%1,%2,%3};"
                 : "+f"(c0), "+f"(c1), "+f"(c2), "+f"(c3)
                 : "r"(a0), "r"(a1), "r"(a2), "r"(a3), "r"(b0), "r"(b1));
}
__device__ __forceinline__ void cp_async16(uint32_t dst, const void* src) {
    asm volatile("cp.async.cg.shared.global [%0], [%1], 16;" :: "r"(dst), "l"(src));
}
#define CP_COMMIT() asm volatile("cp.async.commit_group;" ::: "memory")
#define CP_WAIT0()  asm volatile("cp.async.wait_group 0;" ::: "memory")

// ---------------------------------------------------------------------------
// Kernel 0: adj -> bitmask
// ---------------------------------------------------------------------------
__global__ __launch_bounds__(64) void adjbits_kernel(const int* __restrict__ adj)
{
    const int row = blockIdx.x, w = threadIdx.x;
    const int4* p = (const int4*)(adj + (size_t)row * NN + w * 32);
    uint32_t bits = 0;
#pragma unroll
    for (int q = 0; q < 8; q++) {
        int4 v = __ldg(p + q);
        bits |= (v.x ? 1u : 0u) << (q * 4 + 0);
        bits |= (v.y ? 1u : 0u) << (q * 4 + 1);
        bits |= (v.z ? 1u : 0u) << (q * 4 + 2);
        bits |= (v.w ? 1u : 0u) << (q * 4 + 3);
    }
    g_adjbits[row * (NN / 32) + w] = bits;
}

// ---------------------------------------------------------------------------
// Kernel 1: Wh = h @ W^T + b  (register-tiled fp32 GEMM)
// ---------------------------------------------------------------------------
__global__ __launch_bounds__(256) void wh2_kernel(const float* __restrict__ h,
                                                  const float* __restrict__ Ww,
                                                  const float* __restrict__ Wb)
{
    __shared__ float As[32][32];
    __shared__ float Bs[32][128];
    const int t     = threadIdx.x;
    const int grow0 = blockIdx.x * 32;
    const int col   = (t & 31) * 4;
    const int row0  = (t >> 5) * 4;

    float acc[4][4];
#pragma unroll
    for (int r = 0; r < 4; r++)
#pragma unroll
        for (int c = 0; c < 4; c++) acc[r][c] = 0.f;

    for (int kb = 0; kb < FIN; kb += 32) {
        {
            int r = t >> 3, k4 = (t & 7) * 4;
            *(float4*)&As[r][k4] =
                *(const float4*)(h + (size_t)(grow0 + r) * FIN + kb + k4);
        }
        {
            int o = t >> 1, kh = (t & 1) * 16;
#pragma unroll
            for (int s2 = 0; s2 < 4; s2++) {
                float4 v = *(const float4*)(Ww + (size_t)o * FIN + kb + kh + s2 * 4);
                Bs[kh + s2 * 4 + 0][o] = v.x;
                Bs[kh + s2 * 4 + 1][o] = v.y;
                Bs[kh + s2 * 4 + 2][o] = v.z;
                Bs[kh + s2 * 4 + 3][o] = v.w;
            }
        }
        __syncthreads();
#pragma unroll
        for (int k = 0; k < 32; k++) {
            float4 bv = *(const float4*)&Bs[k][col];
            float a0 = As[row0 + 0][k], a1 = As[row0 + 1][k];
            float a2 = As[row0 + 2][k], a3 = As[row0 + 3][k];
            acc[0][0] += a0 * bv.x; acc[0][1] += a0 * bv.y; acc[0][2] += a0 * bv.z; acc[0][3] += a0 * bv.w;
            acc[1][0] += a1 * bv.x; acc[1][1] += a1 * bv.y; acc[1][2] += a1 * bv.z; acc[1][3] += a1 * bv.w;
            acc[2][0] += a2 * bv.x; acc[2][1] += a2 * bv.y; acc[2][2] += a2 * bv.z; acc[2][3] += a2 * bv.w;
            acc[3][0] += a3 * bv.x; acc[3][1] += a3 * bv.y; acc[3][2] += a3 * bv.z; acc[3][3] += a3 * bv.w;
        }
        __syncthreads();
    }

    float4 bias = *(const float4*)(Wb + col);
    const float bc[4] = {bias.x, bias.y, bias.z, bias.w};
#pragma unroll
    for (int r = 0; r < 4; r++) {
        float4 o4 = make_float4(acc[r][0] + bc[0], acc[r][1] + bc[1],
                                acc[r][2] + bc[2], acc[r][3] + bc[3]);
        *(float4*)(g_Wh + (size_t)(grow0 + row0 + r) * FOUT + col) = o4;
    }
}

// ---------------------------------------------------------------------------
// Kernel 2: per (b,h,n): el/er dot products + exps (exact fp32)
// ---------------------------------------------------------------------------
__global__ __launch_bounds__(256) void pack_kernel(const float* __restrict__ attn_w)
{
    const int t    = threadIdx.x;
    const int warp = t >> 5;
    const int lane = t & 31;
    const int row  = blockIdx.x * 8 + warp;
    const int b    = row >> 11;
    const int n    = row & (NN - 1);

    float4 wh = *(const float4*)(g_Wh + (size_t)row * FOUT + lane * 4);
#pragma unroll
    for (int hh = 0; hh < HH; hh++) {
        float4 al = *(const float4*)(attn_w + hh * 2 * FOUT + lane * 4);
        float4 ar = *(const float4*)(attn_w + hh * 2 * FOUT + FOUT + lane * 4);
        float sl = wh.x * al.x + wh.y * al.y + wh.z * al.z + wh.w * al.w;
        float sr = wh.x * ar.x + wh.y * ar.y + wh.z * ar.z + wh.w * ar.w;
#pragma unroll
        for (int off = 16; off > 0; off >>= 1) {
            sl += __shfl_xor_sync(0xffffffffu, sl, off);
            sr += __shfl_xor_sync(0xffffffffu, sr, off);
        }
        if (lane == 0) {
            const int idx = (b * HH + hh) * NN + n;
            g_ipack[idx] = make_float4(sl, expf(sl), expf(NEG * sl), 0.f);
            g_jpack[idx] = make_float4(sr, expf(sr), expf(NEG * sr), 0.f);
        }
    }
}

// ---------------------------------------------------------------------------
// Kernel 3: repack Wh into paired B-fragments (tf32).
// Tile slot s (0..1023): lane=s&31, ntp=(s>>5)&7, ks=s>>8.
//   x = Wh[j][o0], y = Wh[j+4][o0], z = Wh[j][o1], w = Wh[j+4][o1]
// with j = jt*32 + ks*8 + (lane&3), o0 = (2ntp)*8 + lane/4, o1 = o0 + 8.
// ---------------------------------------------------------------------------
__global__ __launch_bounds__(256) void bfrag_kernel()
{
    const int jt = blockIdx.x, b = blockIdx.y, t = threadIdx.x;
    const size_t base = ((size_t)b * NT + jt) * 1024;
#pragma unroll
    for (int q = 0; q < 4; q++) {
        const int s    = q * 256 + t;
        const int lane = s & 31;
        const int ntp  = (s >> 5) & 7;
        const int ks   = s >> 8;
        const int j    = jt * TK + ks * 8 + (lane & 3);
        const int o0   = (ntp * 2) * 8 + (lane >> 2);
        const int o1   = o0 + 8;
        float x = __ldg(&g_Wh[((size_t)(b * NN + j))     * FOUT + o0]);
        float y = __ldg(&g_Wh[((size_t)(b * NN + j + 4)) * FOUT + o0]);
        float z = __ldg(&g_Wh[((size_t)(b * NN + j))     * FOUT + o1]);
        float w = __ldg(&g_Wh[((size_t)(b * NN + j + 4)) * FOUT + o1]);
        g_Bfrag4[base + s] = make_uint4(f2tf32(x), f2tf32(y), f2tf32(z), f2tf32(w));
    }
}

// ---------------------------------------------------------------------------
// Kernel 4 (main): pipelined P @ Wh via mma.sync tf32.
// Block = (b, 32 i-rows); M=128 packs 4 heads (m = i*4 + h); N = FOUT.
// 8 warps in 2x4, warp tile 64x32. cp.async stages B-frags + jpack tiles.
// ---------------------------------------------------------------------------
// SMEM: Af[2][8][4][32] float4 (32K) | Bf[2][4][8][32] uint4 (32K)
//     | JP[2][4*36] float4 (4608)   | zb[128] (512)
#define SM_A(p, w, ks, ln)   ((((p) * 8 + (w)) * 4 + (ks)) * 32 + (ln))
#define SM_B4(p, ks, ntp, ln) ((((p) * 4 + (ks)) * 8 + (ntp)) * 32 + (ln))
#define OFF_BF 32768
#define OFF_JP 65536
#define OFF_ZB (65536 + 4608)
#define SMEM_BYTES (OFF_ZB + 512)

__global__ __launch_bounds__(256, 2) void gat_main_mma(float* __restrict__ out)
{
    extern __shared__ char smem[];
    float4* Af  = (float4*)smem;
    uint4*  Bf  = (uint4*)(smem + OFF_BF);
    float4* JPf = (float4*)(smem + OFF_JP);
    float*  zb  = (float*)(smem + OFF_ZB);
    const uint32_t Bf_sa = (uint32_t)__cvta_generic_to_shared(Bf);
    const uint32_t JP_sa = (uint32_t)__cvta_generic_to_shared(JPf);

    const int t    = threadIdx.x;
    const int w    = t >> 5;
    const int lane = t & 31;
    const int mw   = w >> 2;            // 0..1
    const int nw   = w & 3;             // 0..3
    const int b    = blockIdx.y;
    const int i0   = blockIdx.x * 32;

    const int r = lane >> 2;            // 0..7
    const int c = lane & 3;             // 0..3
    const int h = r & 3;
    const int iloc_lo = w * 4 + (r >> 2);
    const int iloc_hi = iloc_lo + 2;

    const float4 ipl = __ldg(&g_ipack[(size_t)(b * HH + h) * NN + i0 + iloc_lo]);
    const float4 iph = __ldg(&g_ipack[(size_t)(b * HH + h) * NN + i0 + iloc_hi]);
    const uint4*    bbase  = g_Bfrag4 + (size_t)b * NT * 1024;
    const uint32_t* mbase_lo = g_adjbits + (size_t)(i0 + iloc_lo) * 64;
    const uint32_t* mbase_hi = g_adjbits + (size_t)(i0 + iloc_hi) * 64;

    float z_lo = 0.f, z_hi = 0.f;
    float acc[4][4][4];
#pragma unroll
    for (int a = 0; a < 4; a++)
#pragma unroll
        for (int n = 0; n < 4; n++)
#pragma unroll
            for (int k = 0; k < 4; k++) acc[a][n][k] = 0.f;

    // ---- issue cp.async for tile jn into buffer q ----
    auto stage = [&](int jn, int q) {
        const uint4* src = bbase + (size_t)jn * 1024;
        const uint32_t bdst = Bf_sa + (uint32_t)(q * 1024) * 16u;
#pragma unroll
        for (int k4 = 0; k4 < 4; k4++)
            cp_async16(bdst + (uint32_t)(k4 * 256 + t) * 16u, src + k4 * 256 + t);
        if (t < 128) {
            const int hh = t >> 5, jj = t & 31;
            cp_async16(JP_sa + (uint32_t)(q * 144 + hh * 36 + jj) * 16u,
                       &g_jpack[(size_t)(b * HH + hh) * NN + jn * TK + jj]);
        }
        CP_COMMIT();
    };

    // ---- generate A fragments for tile jt into Af[p] (reads JP[p]) ----
    auto agen = [&](int p, uint32_t m_lo, uint32_t m_hi) {
#pragma unroll
        for (int ks = 0; ks < 4; ks++) {
            float4 jp0 = JPf[p * 144 + h * 36 + ks * 8 + c];
            float4 jp4 = JPf[p * 144 + h * 36 + ks * 8 + c + 4];

            float v0 = (ipl.x + jp0.x > 0.f) ? ipl.y * jp0.y : ipl.z * jp0.z;
            float v1 = (iph.x + jp0.x > 0.f) ? iph.y * jp0.y : iph.z * jp0.z;
            float v2 = (ipl.x + jp4.x > 0.f) ? ipl.y * jp4.y : ipl.z * jp4.z;
            float v3 = (iph.x + jp4.x > 0.f) ? iph.y * jp4.y : iph.z * jp4.z;

            v0 = ((m_lo >> (ks * 8 + c))     & 1u) ? v0 : 0.f;
            v1 = ((m_hi >> (ks * 8 + c))     & 1u) ? v1 : 0.f;
            v2 = ((m_lo >> (ks * 8 + c + 4)) & 1u) ? v2 : 0.f;
            v3 = ((m_hi >> (ks * 8 + c + 4)) & 1u) ? v3 : 0.f;

            z_lo += v0 + v2;
            z_hi += v1 + v3;

            Af[SM_A(p, w, ks, lane)] =
                make_float4(__uint_as_float(f2tf32(v0)), __uint_as_float(f2tf32(v1)),
                            __uint_as_float(f2tf32(v2)), __uint_as_float(f2tf32(v3)));
        }
    };

    // ---- consume tile in buffer p ----
    auto consume = [&](int p) {
#pragma unroll
        for (int ks = 0; ks < 4; ks++) {
            uint4 a[4];
#pragma unroll
            for (int mt = 0; mt < 4; mt++)
                a[mt] = *(uint4*)&Af[SM_A(p, mw * 4 + mt, ks, lane)];
            uint4 b0 = Bf[SM_B4(p, ks, nw * 2 + 0, lane)];
            uint4 b1 = Bf[SM_B4(p, ks, nw * 2 + 1, lane)];
#pragma unroll
            for (int mt = 0; mt < 4; mt++) {
                mma_tf32(acc[mt][0][0], acc[mt][0][1], acc[mt][0][2], acc[mt][0][3],
                         a[mt].x, a[mt].y, a[mt].z, a[mt].w, b0.x, b0.y);
                mma_tf32(acc[mt][1][0], acc[mt][1][1], acc[mt][1][2], acc[mt][1][3],
                         a[mt].x, a[mt].y, a[mt].z, a[mt].w, b0.z, b0.w);
                mma_tf32(acc[mt][2][0], acc[mt][2][1], acc[mt][2][2], acc[mt][2][3],
                         a[mt].x, a[mt].y, a[mt].z, a[mt].w, b1.x, b1.y);
                mma_tf32(acc[mt][3][0], acc[mt][3][1], acc[mt][3][2], acc[mt][3][3],
                         a[mt].x, a[mt].y, a[mt].z, a[mt].w, b1.z, b1.w);
            }
        }
    };

    // ---- prologue: stage tile 0 into buffer 0 ----
    stage(0, 0);
    uint32_t ml_cur = __ldg(mbase_lo + 0);
    uint32_t mh_cur = __ldg(mbase_hi + 0);
    CP_WAIT0();
    __syncthreads();

    // ---- pipelined mainloop ----
    for (int jt = 0; jt < NT; jt++) {
        const int p = jt & 1, q = p ^ 1;

        agen(p, ml_cur, mh_cur);          // Af[p] from JP[p]
        __syncthreads();                  // Af[p] visible to all

        uint32_t ml_nxt = 0, mh_nxt = 0;
        if (jt + 1 < NT) {
            stage(jt + 1, q);             // cp.async into [q], hidden by consume
            ml_nxt = __ldg(mbase_lo + jt + 1);
            mh_nxt = __ldg(mbase_hi + jt + 1);
        }

        consume(p);

        if (jt + 1 < NT) CP_WAIT0();
        __syncthreads();                  // [q] buffers visible for next agen/consume
        ml_cur = ml_nxt; mh_cur = mh_nxt;
    }

    // ---- Z reduction ----
    z_lo += __shfl_xor_sync(0xffffffffu, z_lo, 1);
    z_lo += __shfl_xor_sync(0xffffffffu, z_lo, 2);
    z_hi += __shfl_xor_sync(0xffffffffu, z_hi, 1);
    z_hi += __shfl_xor_sync(0xffffffffu, z_hi, 2);
    if (c == 0) {
        zb[w * 16 + r]     = z_lo;
        zb[w * 16 + r + 8] = z_hi;
    }
    __syncthreads();

    // ---- epilogue: 0.25/Z scale, head reduction, ReLU, store ----
#pragma unroll
    for (int mt = 0; mt < 4; mt++) {
        const int mtile = mw * 4 + mt;
        const int m_a = mtile * 16 + r;
        const int m_b = m_a + 8;
        float zA = zb[m_a], zB = zb[m_b];
        float izA = (zA > 0.f) ? 0.25f / zA : 0.f;
        float izB = (zB > 0.f) ? 0.25f / zB : 0.f;
#pragma unroll
        for (int nt = 0; nt < 4; nt++) {
            float s0 = acc[mt][nt][0] * izA;
            float s1 = acc[mt][nt][1] * izA;
            float s2 = acc[mt][nt][2] * izB;
            float s3 = acc[mt][nt][3] * izB;
            s0 += __shfl_xor_sync(0xffffffffu, s0, 4);
            s0 += __shfl_xor_sync(0xffffffffu, s0, 8);
            s1 += __shfl_xor_sync(0xffffffffu, s1, 4);
            s1 += __shfl_xor_sync(0xffffffffu, s1, 8);
            s2 += __shfl_xor_sync(0xffffffffu, s2, 4);
            s2 += __shfl_xor_sync(0xffffffffu, s2, 8);
            s3 += __shfl_xor_sync(0xffffffffu, s3, 4);
            s3 += __shfl_xor_sync(0xffffffffu, s3, 8);
            if ((r & 3) == 0) {
                const int i_a = mtile * 4 + (r >> 2);
                const int i_b = i_a + 2;
                const int col = nw * 32 + nt * 8 + c * 2;
                float2 oa = make_float2(fmaxf(s0, 0.f), fmaxf(s1, 0.f));
                float2 ob = make_float2(fmaxf(s2, 0.f), fmaxf(s3, 0.f));
                *(float2*)(out + ((size_t)(b * NN + i0 + i_a)) * FOUT + col) = oa;
                *(float2*)(out + ((size_t)(b * NN + i0 + i_b)) * FOUT + col) = ob;
            }
        }
    }
}

// ---------------------------------------------------------------------------
extern "C" void kernel_launch(void* const* d_in, const int* in_sizes, int n_in,
                              void* d_out, int out_size)
{
    const float* h      = (const float*)d_in[0];
    const int*   adj    = (const int*)d_in[1];
    const float* W_w    = (const float*)d_in[2];
    const float* W_b    = (const float*)d_in[3];
    const float* attn_w = (const float*)d_in[4];
    float* out = (float*)d_out;

    adjbits_kernel<<<NN, 64>>>(adj);
    wh2_kernel<<<(Bb * NN) / 32, 256>>>(h, W_w, W_b);
    pack_kernel<<<(Bb * NN) / 8, 256>>>(attn_w);
    bfrag_kernel<<<dim3(NT, Bb), 256>>>();

    cudaFuncSetAttribute(gat_main_mma,
                         cudaFuncAttributeMaxDynamicSharedMemorySize, SMEM_BYTES);
    gat_main_mma<<<dim3(NN / 32, Bb), 256, SMEM_BYTES>>>(out);
}